// round 10
// baseline (speedup 1.0000x reference)
#include <cuda_runtime.h>

// ---------------------------------------------------------------------------
// MWDLSTMGCT: only the L->L wavelet path + LSTM3 are live (output = last time
// index of concat == s3 final h).
//   GEMM1: sig(x @ W1L^T + b1L) -> avgpool2 -> xl1 (256x512)
//   GEMM2: sig(xl1 @ W2L^T + b2L) -> avgpool2 -> xl2 (256x256)
//   LSTM3: T=256 steps, H=100, scalar input per step
//   out[b] = h_final[b] . Wout + bout
// ---------------------------------------------------------------------------

#define BATCH 256
#define HID   100
#define G4    400
#define T3    256

__device__ float g_xl1[BATCH * 512];
__device__ float g_xl2[BATCH * 256];

__device__ __forceinline__ float sigf(float x) {
    return 1.0f / (1.0f + __expf(-x));
}

__device__ __forceinline__ float tanh_fast(float x) {
    float xc = fminf(fmaxf(x, -15.0f), 15.0f);
    float e  = __expf(2.0f * xc);
    return __fdividef(e - 1.0f, e + 1.0f);
}

// packed f32x2 FMA (Blackwell; only reachable via PTX)
__device__ __forceinline__ unsigned long long fma2(unsigned long long a,
                                                   unsigned long long b,
                                                   unsigned long long c) {
    unsigned long long d;
    asm("fma.rn.f32x2 %0, %1, %2, %3;" : "=l"(d) : "l"(a), "l"(b), "l"(c));
    return d;
}

__device__ __forceinline__ float2 unpack2(unsigned long long a) {
    float2 r;
    asm("mov.b64 {%0, %1}, %2;" : "=f"(r.x), "=f"(r.y) : "l"(a));
    return r;
}

// ---------------------------------------------------------------------------
// out_pooled[M x N/2] = avgpool2( sigmoid( A[MxK] @ W[NxK]^T + bias[N] ) )
// BM=32, BN=64, BK=32, 128 threads, 4x4 micro-tile, k-major smem (LDS.128
// operand fetch). BK=32 makes per-tile compute (~1000 cyc/warp) exceed the
// L2/DRAM prefetch latency so the double-buffered pipeline never stalls.
// ---------------------------------------------------------------------------
#define GBM 32
#define GBN 64
#define GBK 32
#define APAD 36
#define WPAD 68

__global__ __launch_bounds__(128)
void gemm_sig_pool(const float* __restrict__ A, const float* __restrict__ W,
                   const float* __restrict__ bias, float* __restrict__ out,
                   int K, int N) {
    __shared__ float As[2][GBK * APAD];
    __shared__ float Ws[2][GBK * WPAD];

    int tid = threadIdx.x;          // 0..127
    int tx = tid & 15;              // n group: cols tx*4..+3
    int ty = tid >> 4;              // m group: rows ty*4..+3
    int m0 = blockIdx.x * GBM;
    int n0 = blockIdx.y * GBN;

    int lr = tid >> 2;              // 0..31
    int lq = (tid & 3) * 4;         // k offset {0,4,8,12}; +16 for 2nd half

    const float* Ag  = A + (m0 + lr) * K + lq;
    const float* Wg0 = W + (n0 + lr) * K + lq;
    const float* Wg1 = W + (n0 + lr + 32) * K + lq;

    float4 pa0, pa1, pw00, pw01, pw10, pw11;
    pa0  = *(const float4*)Ag;
    pa1  = *(const float4*)(Ag + 16);
    pw00 = *(const float4*)Wg0;
    pw01 = *(const float4*)(Wg0 + 16);
    pw10 = *(const float4*)Wg1;
    pw11 = *(const float4*)(Wg1 + 16);

    #define SCATTER(buf)                                                     \
    {                                                                        \
        float* as = &As[buf][0];                                             \
        float* ws = &Ws[buf][0];                                             \
        as[(lq + 0) * APAD + lr] = pa0.x;  as[(lq + 1) * APAD + lr] = pa0.y; \
        as[(lq + 2) * APAD + lr] = pa0.z;  as[(lq + 3) * APAD + lr] = pa0.w; \
        as[(lq + 16) * APAD + lr] = pa1.x; as[(lq + 17) * APAD + lr] = pa1.y;\
        as[(lq + 18) * APAD + lr] = pa1.z; as[(lq + 19) * APAD + lr] = pa1.w;\
        ws[(lq + 0) * WPAD + lr] = pw00.x; ws[(lq + 1) * WPAD + lr] = pw00.y;\
        ws[(lq + 2) * WPAD + lr] = pw00.z; ws[(lq + 3) * WPAD + lr] = pw00.w;\
        ws[(lq + 16) * WPAD + lr] = pw01.x; ws[(lq + 17) * WPAD + lr] = pw01.y;\
        ws[(lq + 18) * WPAD + lr] = pw01.z; ws[(lq + 19) * WPAD + lr] = pw01.w;\
        ws[(lq + 0) * WPAD + lr + 32] = pw10.x; ws[(lq + 1) * WPAD + lr + 32] = pw10.y;\
        ws[(lq + 2) * WPAD + lr + 32] = pw10.z; ws[(lq + 3) * WPAD + lr + 32] = pw10.w;\
        ws[(lq + 16) * WPAD + lr + 32] = pw11.x; ws[(lq + 17) * WPAD + lr + 32] = pw11.y;\
        ws[(lq + 18) * WPAD + lr + 32] = pw11.z; ws[(lq + 19) * WPAD + lr + 32] = pw11.w;\
    }

    SCATTER(0)

    float acc[4][4];
#pragma unroll
    for (int i = 0; i < 4; i++)
#pragma unroll
        for (int j = 0; j < 4; j++) acc[i][j] = 0.0f;

    int ntiles = K / GBK;
    for (int t = 0; t < ntiles; t++) {
        __syncthreads();
        int cur = t & 1;

        if (t + 1 < ntiles) {                 // prefetch next tile into regs
            int ko = (t + 1) * GBK;
            pa0  = *(const float4*)(Ag + ko);
            pa1  = *(const float4*)(Ag + ko + 16);
            pw00 = *(const float4*)(Wg0 + ko);
            pw01 = *(const float4*)(Wg0 + ko + 16);
            pw10 = *(const float4*)(Wg1 + ko);
            pw11 = *(const float4*)(Wg1 + ko + 16);
        }

        const float* as = &As[cur][0];
        const float* ws = &Ws[cur][0];
#pragma unroll
        for (int k = 0; k < GBK; k++) {
            float4 a = *(const float4*)(as + k * APAD + ty * 4);
            float4 w = *(const float4*)(ws + k * WPAD + tx * 4);
            acc[0][0] += a.x * w.x; acc[0][1] += a.x * w.y;
            acc[0][2] += a.x * w.z; acc[0][3] += a.x * w.w;
            acc[1][0] += a.y * w.x; acc[1][1] += a.y * w.y;
            acc[1][2] += a.y * w.z; acc[1][3] += a.y * w.w;
            acc[2][0] += a.z * w.x; acc[2][1] += a.z * w.y;
            acc[2][2] += a.z * w.z; acc[2][3] += a.z * w.w;
            acc[3][0] += a.w * w.x; acc[3][1] += a.w * w.y;
            acc[3][2] += a.w * w.z; acc[3][3] += a.w * w.w;
        }

        if (t + 1 < ntiles) {
            int nx = (t + 1) & 1;
            SCATTER(nx)
        }
    }
    #undef SCATTER

    int halfN = N >> 1;
#pragma unroll
    for (int i = 0; i < 4; i++) {
        int m = m0 + ty * 4 + i;
#pragma unroll
        for (int j = 0; j < 2; j++) {
            int n = n0 + tx * 4 + j * 2;
            float v0 = sigf(acc[i][j * 2]     + bias[n]);
            float v1 = sigf(acc[i][j * 2 + 1] + bias[n + 1]);
            out[m * halfN + (n >> 1)] = 0.5f * (v0 + v1);
        }
    }
}

// ---------------------------------------------------------------------------
// LSTM3: 128 blocks x 2 batch elements, 416 threads (t<400 active).
// Thread t owns Whh row (u + q*100), u=t>>2, q=t&3 (0=i,1=f,2=g,3=o):
// all 4 gates of unit u live in 4 adjacent lanes of one warp.
// Per step, per elem: in-register matvec (50 fma2), then 3 shfl_xor gather
// the gate pre-activations; lane q0 updates elem A's cell, lane q1 elem B's.
// h is double-buffered -> ONE __syncthreads per step, no z smem.
// ---------------------------------------------------------------------------
__global__ __launch_bounds__(416, 1)
void lstm_kernel(const float* __restrict__ xin,   // [BATCH, 256] = g_xl2
                 const float* __restrict__ Wih,   // [400,1]
                 const float* __restrict__ Whh,   // [400,100]
                 const float* __restrict__ b,     // [400]
                 const float* __restrict__ Wout,  // [1,100]
                 const float* __restrict__ bout,  // [1]
                 float* __restrict__ out) {       // [BATCH]
    __shared__ alignas(16) float hA[2][104];
    __shared__ alignas(16) float hB[2][104];
    __shared__ float xA[T3];
    __shared__ float xB[T3];
    __shared__ float red[208];

    int t  = threadIdx.x;
    int bA = blockIdx.x * 2;
    int bB = bA + 1;

    bool act = (t < G4);
    int u = t >> 2;                  // unit 0..99
    int q = t & 3;                   // 0=i 1=f 2=g 3=o
    int row = act ? (u + q * 100) : 0;

    for (int i = t; i < T3; i += 416) {
        xA[i] = xin[bA * T3 + i];
        xB[i] = xin[bB * T3 + i];
    }
    if (t < 104) { hA[0][t] = 0.0f; hB[0][t] = 0.0f; }

    // weight-stationary: Whh row in 50 packed f32x2 regs
    unsigned long long wp[50];
    {
        const unsigned long long* wr =
            (const unsigned long long*)(Whh + row * HID);   // rows 400B, 16B aligned
#pragma unroll
        for (int k = 0; k < 50; k++) wp[k] = wr[k];
    }
    float wih_t = Wih[row];
    float b_t   = b[row];

    float c = 0.0f;          // cA on q0 lanes, cB on q1 lanes
    float h_keep = 0.0f;     // latest h (q0: hA[u], q1: hB[u])

    __syncthreads();

    for (int s = 0; s < T3; s++) {
        int cur = s & 1, nxt = cur ^ 1;
        const ulonglong2* hcA = (const ulonglong2*)hA[cur];
        const ulonglong2* hcB = (const ulonglong2*)hB[cur];

        // ---- elem A: matvec + gate update (lane q0 computes) ----
        {
            unsigned long long a0 = 0ull, a1 = 0ull;
#pragma unroll
            for (int k = 0; k < 25; k++) {
                ulonglong2 h = hcA[k];
                a0 = fma2(wp[2 * k],     h.x, a0);
                a1 = fma2(wp[2 * k + 1], h.y, a1);
            }
            float2 f0 = unpack2(a0), f1 = unpack2(a1);
            float z = (f0.x + f0.y) + (f1.x + f1.y) + fmaf(xA[s], wih_t, b_t);

            float r1 = __shfl_xor_sync(0xFFFFFFFFu, z, 1);  // q0<-f, q2<-o
            float tv = 0.0f, sv = 0.0f;
            if (q == 2) { tv = tanh_fast(z); sv = sigf(r1); }
            float tg = __shfl_xor_sync(0xFFFFFFFFu, tv, 2); // q0 <- q2
            float so = __shfl_xor_sync(0xFFFFFFFFu, sv, 2);
            if (act && q == 0) {
                c = sigf(r1) * c + sigf(z) * tg;            // sig(f)*c + sig(i)*tanh(g)
                h_keep = so * tanh_fast(c);
                hA[nxt][u] = h_keep;
            }
        }

        // ---- elem B: matvec + gate update (lane q1 computes) ----
        {
            unsigned long long a0 = 0ull, a1 = 0ull;
#pragma unroll
            for (int k = 0; k < 25; k++) {
                ulonglong2 h = hcB[k];
                a0 = fma2(wp[2 * k],     h.x, a0);
                a1 = fma2(wp[2 * k + 1], h.y, a1);
            }
            float2 f0 = unpack2(a0), f1 = unpack2(a1);
            float z = (f0.x + f0.y) + (f1.x + f1.y) + fmaf(xB[s], wih_t, b_t);

            float r1 = __shfl_xor_sync(0xFFFFFFFFu, z, 1);  // q1<-i, q3<-g
            float tv = 0.0f, sv = 0.0f;
            if (q == 3) { tv = tanh_fast(r1); sv = sigf(z); }
            float tg = __shfl_xor_sync(0xFFFFFFFFu, tv, 2); // q1 <- q3
            float so = __shfl_xor_sync(0xFFFFFFFFu, sv, 2);
            if (act && q == 1) {
                c = sigf(z) * c + sigf(r1) * tg;            // sig(f)*c + sig(i)*tanh(g)
                h_keep = so * tanh_fast(c);
                hB[nxt][u] = h_keep;
            }
        }

        __syncthreads();   // h(nxt) published for next step
    }

    // ---- output projection: out[b] = dot(h(255), Wout) + bout ----
    if (act && q == 0) red[u]       = h_keep * Wout[u];
    if (act && q == 1) red[u + 104] = h_keep * Wout[u];
    __syncthreads();
    if (t == 0) {
        float s1 = 0.0f;
        for (int j = 0; j < HID; j++) s1 += red[j];
        out[bA] = s1 + bout[0];
    } else if (t == 1) {
        float s2 = 0.0f;
        for (int j = 0; j < HID; j++) s2 += red[j + 104];
        out[bB] = s2 + bout[0];
    }
}

// ---------------------------------------------------------------------------
extern "C" void kernel_launch(void* const* d_in, const int* in_sizes, int n_in,
                              void* d_out, int out_size) {
    const float* x    = (const float*)d_in[0];
    const float* W1L  = (const float*)d_in[3];
    const float* b1L  = (const float*)d_in[4];
    const float* W2L  = (const float*)d_in[7];
    const float* b2L  = (const float*)d_in[8];
    const float* Wih3 = (const float*)d_in[15];
    const float* Whh3 = (const float*)d_in[16];
    const float* b3   = (const float*)d_in[17];
    const float* Wout = (const float*)d_in[18];
    const float* bout = (const float*)d_in[19];
    float* out = (float*)d_out;

    float* xl1;
    float* xl2;
    cudaGetSymbolAddress((void**)&xl1, g_xl1);
    cudaGetSymbolAddress((void**)&xl2, g_xl2);

    // Layer 1: x(256x1024) @ W1L^T -> sig -> pool -> xl1(256x512)
    gemm_sig_pool<<<dim3(256 / GBM, 1024 / GBN), 128>>>(x, W1L, b1L, xl1, 1024, 1024);
    // Layer 2: xl1(256x512) @ W2L^T -> sig -> pool -> xl2(256x256)
    gemm_sig_pool<<<dim3(256 / GBM, 512 / GBN), 128>>>(xl1, W2L, b2L, xl2, 512, 512);
    // LSTM3 + output projection
    lstm_kernel<<<BATCH / 2, 416>>>(xl2, Wih3, Whh3, b3, Wout, bout, out);
}

// round 11
// speedup vs baseline: 1.2605x; 1.2605x over previous
#include <cuda_runtime.h>

// ---------------------------------------------------------------------------
// MWDLSTMGCT: only the L->L wavelet path + LSTM3 are live (output = last time
// index of concat == s3 final h).
//   GEMM1: sig(x @ W1L^T + b1L) -> avgpool2 -> xl1 (256x512)
//   GEMM2: sig(xl1 @ W2L^T + b2L) -> avgpool2 -> xl2 (256x256)
//   LSTM3: T=256 steps, H=100, scalar input per step
//   out[b] = h_final[b] . Wout + bout
// ---------------------------------------------------------------------------

#define BATCH 256
#define HID   100
#define G4    400
#define T3    256

__device__ float g_xl1[BATCH * 512];
__device__ float g_xl2[BATCH * 256];

// HW tanh (sm_75+; 1 MUFU op)
__device__ __forceinline__ float tanh_hw(float x) {
    float y;
    asm("tanh.approx.f32 %0, %1;" : "=f"(y) : "f"(x));
    return y;
}
// sigmoid via HW tanh: sig(x) = 0.5*tanh(x/2) + 0.5  (1 MUFU + 2 FMA)
__device__ __forceinline__ float sig_hw(float x) {
    return fmaf(tanh_hw(0.5f * x), 0.5f, 0.5f);
}

// packed f32x2 FMA (Blackwell; only reachable via PTX)
__device__ __forceinline__ unsigned long long fma2(unsigned long long a,
                                                   unsigned long long b,
                                                   unsigned long long c) {
    unsigned long long d;
    asm("fma.rn.f32x2 %0, %1, %2, %3;" : "=l"(d) : "l"(a), "l"(b), "l"(c));
    return d;
}

__device__ __forceinline__ float2 unpack2(unsigned long long a) {
    float2 r;
    asm("mov.b64 {%0, %1}, %2;" : "=f"(r.x), "=f"(r.y) : "l"(a));
    return r;
}

// ---------------------------------------------------------------------------
// out_pooled[M x N/2] = avgpool2( sigmoid( A[MxK] @ W[NxK]^T + bias[N] ) )
// BM=16, BN=64, BK=32, 256 threads (8 warps), 1x4 micro-tile.
// Grid GEMM1 = 256 blocks -> ~2 blocks/SM x 8 warps = 4 warps/SMSP: enough
// warp-parallelism to saturate the FFMA pipe (the prior 4-warp/SM configs
// were issue/latency-bound at ~26% issue, invariant across tilings).
// ---------------------------------------------------------------------------
#define GBM 16
#define GBN 64
#define GBK 32
#define WPAD 68

__global__ __launch_bounds__(256)
void gemm_sig_pool(const float* __restrict__ A, const float* __restrict__ W,
                   const float* __restrict__ bias, float* __restrict__ out,
                   int K, int N) {
    __shared__ float As[2][GBK * GBM];
    __shared__ float Ws[2][GBK * WPAD];

    int tid = threadIdx.x;          // 0..255
    int tx = tid & 15;              // n group: cols tx*4..+3
    int ty = tid >> 4;              // m row 0..15
    int m0 = blockIdx.x * GBM;
    int n0 = blockIdx.y * GBN;

    // global-load mapping
    int ar = tid >> 3;              // 0..31 (use 0..15 for A rows)
    int aq = (tid & 7) * 4;         // k offset {0,4,...,28}
    bool loadA = (tid < 128);

    const float* Ag  = A + (m0 + ar) * K + aq;       // valid when loadA
    const float* Wg0 = W + (n0 + ar) * K + aq;       // rows ar, ar+32
    const float* Wg1 = W + (n0 + ar + 32) * K + aq;

    float4 pa, pw0, pw1;
    if (loadA) pa = *(const float4*)Ag;
    pw0 = *(const float4*)Wg0;
    pw1 = *(const float4*)Wg1;

    #define SCATTER(buf)                                                      \
    {                                                                         \
        float* ws = &Ws[buf][0];                                              \
        if (loadA) {                                                          \
            float* as = &As[buf][0];                                          \
            as[(aq + 0) * GBM + ar] = pa.x; as[(aq + 1) * GBM + ar] = pa.y;   \
            as[(aq + 2) * GBM + ar] = pa.z; as[(aq + 3) * GBM + ar] = pa.w;   \
        }                                                                     \
        ws[(aq + 0) * WPAD + ar] = pw0.x; ws[(aq + 1) * WPAD + ar] = pw0.y;   \
        ws[(aq + 2) * WPAD + ar] = pw0.z; ws[(aq + 3) * WPAD + ar] = pw0.w;   \
        ws[(aq + 0) * WPAD + ar + 32] = pw1.x;                                \
        ws[(aq + 1) * WPAD + ar + 32] = pw1.y;                                \
        ws[(aq + 2) * WPAD + ar + 32] = pw1.z;                                \
        ws[(aq + 3) * WPAD + ar + 32] = pw1.w;                                \
    }

    SCATTER(0)

    float acc0 = 0.0f, acc1 = 0.0f, acc2 = 0.0f, acc3 = 0.0f;

    int ntiles = K / GBK;
    for (int t = 0; t < ntiles; t++) {
        __syncthreads();
        int cur = t & 1;

        if (t + 1 < ntiles) {                 // prefetch next tile into regs
            int ko = (t + 1) * GBK;
            if (loadA) pa = *(const float4*)(Ag + ko);
            pw0 = *(const float4*)(Wg0 + ko);
            pw1 = *(const float4*)(Wg1 + ko);
        }

        const float* as = &As[cur][0];
        const float* ws = &Ws[cur][0];
#pragma unroll
        for (int k = 0; k < GBK; k++) {
            float a  = as[k * GBM + ty];
            float4 w = *(const float4*)(ws + k * WPAD + tx * 4);
            acc0 += a * w.x;
            acc1 += a * w.y;
            acc2 += a * w.z;
            acc3 += a * w.w;
        }

        if (t + 1 < ntiles) {
            int nx = (t + 1) & 1;
            SCATTER(nx)
        }
    }
    #undef SCATTER

    // fused sigmoid + avgpool2 epilogue
    int halfN = N >> 1;
    int m = m0 + ty;
    int n = n0 + tx * 4;
    float v0 = sig_hw(acc0 + bias[n]);
    float v1 = sig_hw(acc1 + bias[n + 1]);
    float v2 = sig_hw(acc2 + bias[n + 2]);
    float v3 = sig_hw(acc3 + bias[n + 3]);
    out[m * halfN + (n >> 1)]     = 0.5f * (v0 + v1);
    out[m * halfN + (n >> 1) + 1] = 0.5f * (v2 + v3);
}

// ---------------------------------------------------------------------------
// LSTM3 (proven R9 structure): 128 blocks x 2 batch elements, 416 threads.
// Thread t < 400 owns gate-unit t for BOTH elems: Whh row t in 50 packed
// f32x2 registers, h read via LDS.128 broadcast, 4 interleaved fma2 chains.
// Gate phase: elem A on threads 0..99 (warps 0-3), elem B on threads
// 128..227 (warps 4-7) in parallel; nonlinearities use HW tanh.approx
// (1 MUFU) and tanh-derived sigmoid, shrinking the serial gate region.
// ---------------------------------------------------------------------------
__global__ __launch_bounds__(416, 1)
void lstm_kernel(const float* __restrict__ xin,   // [BATCH, 256] = g_xl2
                 const float* __restrict__ Wih,   // [400,1]
                 const float* __restrict__ Whh,   // [400,100]
                 const float* __restrict__ b,     // [400]
                 const float* __restrict__ Wout,  // [1,100]
                 const float* __restrict__ bout,  // [1]
                 float* __restrict__ out) {       // [BATCH]
    __shared__ alignas(16) float hA[104];
    __shared__ alignas(16) float hB[104];
    __shared__ float zA[G4];
    __shared__ float zB[G4];
    __shared__ float xA[T3];
    __shared__ float xB[T3];
    __shared__ float red[228];

    int t  = threadIdx.x;
    int bA = blockIdx.x * 2;
    int bB = bA + 1;

    // preload per-element input sequences
    for (int i = t; i < T3; i += 416) {
        xA[i] = xin[bA * T3 + i];
        xB[i] = xin[bB * T3 + i];
    }
    if (t < 104) { hA[t] = 0.0f; hB[t] = 0.0f; }

    // weight-stationary: Whh row t in registers (packed pairs)
    unsigned long long wp[50];
    float wih_t = 0.0f, b_t = 0.0f;
    if (t < G4) {
        const unsigned long long* wr =
            (const unsigned long long*)(Whh + t * HID);   // rows 400B, 16B aligned
#pragma unroll
        for (int k = 0; k < 50; k++) wp[k] = wr[k];
        wih_t = Wih[t];
        b_t   = b[t];
    }

    float c = 0.0f;                          // cA for t<100, cB for t in [128,228)
    int tb = t - 128;
    const ulonglong2* h128A = (const ulonglong2*)hA;
    const ulonglong2* h128B = (const ulonglong2*)hB;

    for (int s = 0; s < T3; s++) {
        __syncthreads();          // h ready for this step
        if (t < G4) {
            unsigned long long a0 = 0ull, a1 = 0ull, d0 = 0ull, d1 = 0ull;
#pragma unroll
            for (int k = 0; k < 25; k++) {
                ulonglong2 ha = h128A[k];
                ulonglong2 hb = h128B[k];
                a0 = fma2(wp[2 * k],     ha.x, a0);
                a1 = fma2(wp[2 * k + 1], ha.y, a1);
                d0 = fma2(wp[2 * k],     hb.x, d0);
                d1 = fma2(wp[2 * k + 1], hb.y, d1);
            }
            float gbase  = fmaf(xA[s], wih_t, b_t);
            float gbaseB = fmaf(xB[s], wih_t, b_t);
            float2 fa0 = unpack2(a0), fa1 = unpack2(a1);
            float2 fb0 = unpack2(d0), fb1 = unpack2(d1);
            zA[t] = (fa0.x + fa0.y) + (fa1.x + fa1.y) + gbase;
            zB[t] = (fb0.x + fb0.y) + (fb1.x + fb1.y) + gbaseB;
        }
        __syncthreads();          // z complete
        if (t < HID) {
            float iv = sig_hw(zA[t]);
            float fv = sig_hw(zA[t + 100]);
            float gv = tanh_hw(zA[t + 200]);
            float ov = sig_hw(zA[t + 300]);
            c = fv * c + iv * gv;
            hA[t] = ov * tanh_hw(c);
        } else if (tb >= 0 && tb < HID) {
            float iv = sig_hw(zB[tb]);
            float fv = sig_hw(zB[tb + 100]);
            float gv = tanh_hw(zB[tb + 200]);
            float ov = sig_hw(zB[tb + 300]);
            c = fv * c + iv * gv;
            hB[tb] = ov * tanh_hw(c);
        }
    }

    __syncthreads();
    if (t < HID) {
        red[t] = hA[t] * Wout[t];
    } else if (tb >= 0 && tb < HID) {
        red[tb + 114] = hB[tb] * Wout[tb];
    }
    __syncthreads();
    if (t == 0) {
        float s1 = 0.0f;
        for (int j = 0; j < HID; j++) s1 += red[j];
        out[bA] = s1 + bout[0];
    } else if (t == 128) {
        float s2 = 0.0f;
        for (int j = 0; j < HID; j++) s2 += red[j + 114];
        out[bB] = s2 + bout[0];
    }
}

// ---------------------------------------------------------------------------
extern "C" void kernel_launch(void* const* d_in, const int* in_sizes, int n_in,
                              void* d_out, int out_size) {
    const float* x    = (const float*)d_in[0];
    const float* W1L  = (const float*)d_in[3];
    const float* b1L  = (const float*)d_in[4];
    const float* W2L  = (const float*)d_in[7];
    const float* b2L  = (const float*)d_in[8];
    const float* Wih3 = (const float*)d_in[15];
    const float* Whh3 = (const float*)d_in[16];
    const float* b3   = (const float*)d_in[17];
    const float* Wout = (const float*)d_in[18];
    const float* bout = (const float*)d_in[19];
    float* out = (float*)d_out;

    float* xl1;
    float* xl2;
    cudaGetSymbolAddress((void**)&xl1, g_xl1);
    cudaGetSymbolAddress((void**)&xl2, g_xl2);

    // Layer 1: x(256x1024) @ W1L^T -> sig -> pool -> xl1(256x512)
    gemm_sig_pool<<<dim3(256 / GBM, 1024 / GBN), 256>>>(x, W1L, b1L, xl1, 1024, 1024);
    // Layer 2: xl1(256x512) @ W2L^T -> sig -> pool -> xl2(256x256)
    gemm_sig_pool<<<dim3(256 / GBM, 512 / GBN), 256>>>(xl1, W2L, b2L, xl2, 512, 512);
    // LSTM3 + output projection
    lstm_kernel<<<BATCH / 2, 416>>>(xl2, Wih3, Whh3, b3, Wout, bout, out);
}

// round 14
// speedup vs baseline: 1.3928x; 1.1050x over previous
#include <cuda_runtime.h>

// ---------------------------------------------------------------------------
// MWDLSTMGCT: only the L->L wavelet path + LSTM3 are live (output = last time
// index of concat == s3 final h).
//   GEMM1: sig(x @ W1L^T + b1L) -> avgpool2 -> xl1 (256x512)
//   GEMM2: sig(xl1 @ W2L^T + b2L) -> avgpool2 -> xl2 (256x256)
//   LSTM3: T=256 steps, H=100, scalar input per step
//   out[b] = h_final[b] . Wout + bout
// ---------------------------------------------------------------------------

#define BATCH 256
#define HID   100
#define G4    400
#define T3    256

__device__ float g_xl1[BATCH * 512];
__device__ float g_xl2[BATCH * 256];

// HW tanh (1 MUFU op)
__device__ __forceinline__ float tanh_hw(float x) {
    float y;
    asm("tanh.approx.f32 %0, %1;" : "=f"(y) : "f"(x));
    return y;
}
// sigmoid via HW tanh: sig(x) = 0.5*tanh(x/2) + 0.5
__device__ __forceinline__ float sig_hw(float x) {
    return fmaf(tanh_hw(0.5f * x), 0.5f, 0.5f);
}

// packed f32x2 FMA (Blackwell; only reachable via PTX)
__device__ __forceinline__ unsigned long long fma2(unsigned long long a,
                                                   unsigned long long b,
                                                   unsigned long long c) {
    unsigned long long d;
    asm("fma.rn.f32x2 %0, %1, %2, %3;" : "=l"(d) : "l"(a), "l"(b), "l"(c));
    return d;
}

__device__ __forceinline__ float2 unpack2(unsigned long long a) {
    float2 r;
    asm("mov.b64 {%0, %1}, %2;" : "=f"(r.x), "=f"(r.y) : "l"(a));
    return r;
}

// ---------------------------------------------------------------------------
// out_pooled[M x N/2] = avgpool2( sigmoid( A[MxK] @ W[NxK]^T + bias[N] ) )
// BM=32, BN=64, BK=32, 256 threads (8 warps), 2x4 micro-tile.
//   - 8 FFMA per (1 LDS.64 bcast + 1 LDS.128) per k  -> fma-pipe bound
//   - 2 warps/SMSP to hide sync/prefetch latency (R9 had 1, issue=26%)
//   - k-major smem, double-buffered, register prefetch
// ---------------------------------------------------------------------------
#define GBM 32
#define GBN 64
#define GBK 32
#define APAD 34
#define WPAD 68

__global__ __launch_bounds__(256)
void gemm_sig_pool(const float* __restrict__ A, const float* __restrict__ W,
                   const float* __restrict__ bias, float* __restrict__ out,
                   int K, int N) {
    __shared__ float As[2][GBK * APAD];
    __shared__ float Ws[2][GBK * WPAD];

    int tid = threadIdx.x;          // 0..255
    int tx = tid & 15;              // n group: cols tx*4..+3
    int ty = tid >> 4;              // m group: rows ty*2, ty*2+1
    int m0 = blockIdx.x * GBM;
    int n0 = blockIdx.y * GBN;

    // global-load mapping: 1 float4 of A + 2 float4 of W per thread
    int ar = tid >> 3;              // 0..31
    int aq = (tid & 7) * 4;         // k offset {0,4,...,28}

    const float* Ag  = A + (m0 + ar) * K + aq;
    const float* Wg0 = W + (n0 + ar) * K + aq;
    const float* Wg1 = W + (n0 + ar + 32) * K + aq;

    float4 pa, pw0, pw1;
    pa  = *(const float4*)Ag;
    pw0 = *(const float4*)Wg0;
    pw1 = *(const float4*)Wg1;

    #define SCATTER(buf)                                                      \
    {                                                                         \
        float* as = &As[buf][0];                                              \
        float* ws = &Ws[buf][0];                                              \
        as[(aq + 0) * APAD + ar] = pa.x;  as[(aq + 1) * APAD + ar] = pa.y;    \
        as[(aq + 2) * APAD + ar] = pa.z;  as[(aq + 3) * APAD + ar] = pa.w;    \
        ws[(aq + 0) * WPAD + ar] = pw0.x; ws[(aq + 1) * WPAD + ar] = pw0.y;   \
        ws[(aq + 2) * WPAD + ar] = pw0.z; ws[(aq + 3) * WPAD + ar] = pw0.w;   \
        ws[(aq + 0) * WPAD + ar + 32] = pw1.x;                                \
        ws[(aq + 1) * WPAD + ar + 32] = pw1.y;                                \
        ws[(aq + 2) * WPAD + ar + 32] = pw1.z;                                \
        ws[(aq + 3) * WPAD + ar + 32] = pw1.w;                                \
    }

    SCATTER(0)

    float acc[2][4];
#pragma unroll
    for (int i = 0; i < 2; i++)
#pragma unroll
        for (int j = 0; j < 4; j++) acc[i][j] = 0.0f;

    int ntiles = K / GBK;
    for (int t = 0; t < ntiles; t++) {
        __syncthreads();
        int cur = t & 1;

        if (t + 1 < ntiles) {                 // prefetch next tile into regs
            int ko = (t + 1) * GBK;
            pa  = *(const float4*)(Ag + ko);
            pw0 = *(const float4*)(Wg0 + ko);
            pw1 = *(const float4*)(Wg1 + ko);
        }

        const float* as = &As[cur][0];
        const float* ws = &Ws[cur][0];
#pragma unroll
        for (int k = 0; k < GBK; k++) {
            float2 a = *(const float2*)(as + k * APAD + ty * 2);
            float4 w = *(const float4*)(ws + k * WPAD + tx * 4);
            acc[0][0] += a.x * w.x; acc[0][1] += a.x * w.y;
            acc[0][2] += a.x * w.z; acc[0][3] += a.x * w.w;
            acc[1][0] += a.y * w.x; acc[1][1] += a.y * w.y;
            acc[1][2] += a.y * w.z; acc[1][3] += a.y * w.w;
        }

        if (t + 1 < ntiles) {
            int nx = (t + 1) & 1;
            SCATTER(nx)
        }
    }
    #undef SCATTER

    // fused sigmoid + avgpool2 epilogue
    int halfN = N >> 1;
    int n = n0 + tx * 4;
#pragma unroll
    for (int i = 0; i < 2; i++) {
        int m = m0 + ty * 2 + i;
        float v0 = sig_hw(acc[i][0] + bias[n]);
        float v1 = sig_hw(acc[i][1] + bias[n + 1]);
        float v2 = sig_hw(acc[i][2] + bias[n + 2]);
        float v3 = sig_hw(acc[i][3] + bias[n + 3]);
        out[m * halfN + (n >> 1)]     = 0.5f * (v0 + v1);
        out[m * halfN + (n >> 1) + 1] = 0.5f * (v2 + v3);
    }
}

// ---------------------------------------------------------------------------
// LSTM3 (proven structure + HW-tanh gates): 128 blocks x 2 batch elements,
// 416 threads. Thread t < 400 owns gate-unit t for BOTH elems: Whh row t in
// 50 packed f32x2 registers, h via LDS.128 broadcast, 4 interleaved chains.
// Gate phase: elem A on threads 0..99, elem B on threads 128..227, parallel.
// ---------------------------------------------------------------------------
__global__ __launch_bounds__(416, 1)
void lstm_kernel(const float* __restrict__ xin,   // [BATCH, 256] = g_xl2
                 const float* __restrict__ Wih,   // [400,1]
                 const float* __restrict__ Whh,   // [400,100]
                 const float* __restrict__ b,     // [400]
                 const float* __restrict__ Wout,  // [1,100]
                 const float* __restrict__ bout,  // [1]
                 float* __restrict__ out) {       // [BATCH]
    __shared__ alignas(16) float hA[104];
    __shared__ alignas(16) float hB[104];
    __shared__ float zA[G4];
    __shared__ float zB[G4];
    __shared__ float xA[T3];
    __shared__ float xB[T3];
    __shared__ float red[228];

    int t  = threadIdx.x;
    int bA = blockIdx.x * 2;
    int bB = bA + 1;

    for (int i = t; i < T3; i += 416) {
        xA[i] = xin[bA * T3 + i];
        xB[i] = xin[bB * T3 + i];
    }
    if (t < 104) { hA[t] = 0.0f; hB[t] = 0.0f; }

    unsigned long long wp[50];
    float wih_t = 0.0f, b_t = 0.0f;
    if (t < G4) {
        const unsigned long long* wr =
            (const unsigned long long*)(Whh + t * HID);   // rows 400B, 16B aligned
#pragma unroll
        for (int k = 0; k < 50; k++) wp[k] = wr[k];
        wih_t = Wih[t];
        b_t   = b[t];
    }

    float c = 0.0f;                          // cA for t<100, cB for t in [128,228)
    int tb = t - 128;
    const ulonglong2* h128A = (const ulonglong2*)hA;
    const ulonglong2* h128B = (const ulonglong2*)hB;

    for (int s = 0; s < T3; s++) {
        __syncthreads();          // h ready for this step
        if (t < G4) {
            unsigned long long a0 = 0ull, a1 = 0ull, d0 = 0ull, d1 = 0ull;
#pragma unroll
            for (int k = 0; k < 25; k++) {
                ulonglong2 ha = h128A[k];
                ulonglong2 hb = h128B[k];
                a0 = fma2(wp[2 * k],     ha.x, a0);
                a1 = fma2(wp[2 * k + 1], ha.y, a1);
                d0 = fma2(wp[2 * k],     hb.x, d0);
                d1 = fma2(wp[2 * k + 1], hb.y, d1);
            }
            float gbase  = fmaf(xA[s], wih_t, b_t);
            float gbaseB = fmaf(xB[s], wih_t, b_t);
            float2 fa0 = unpack2(a0), fa1 = unpack2(a1);
            float2 fb0 = unpack2(d0), fb1 = unpack2(d1);
            zA[t] = (fa0.x + fa0.y) + (fa1.x + fa1.y) + gbase;
            zB[t] = (fb0.x + fb0.y) + (fb1.x + fb1.y) + gbaseB;
        }
        __syncthreads();          // z complete
        if (t < HID) {
            float iv = sig_hw(zA[t]);
            float fv = sig_hw(zA[t + 100]);
            float gv = tanh_hw(zA[t + 200]);
            float ov = sig_hw(zA[t + 300]);
            c = fv * c + iv * gv;
            hA[t] = ov * tanh_hw(c);
        } else if (tb >= 0 && tb < HID) {
            float iv = sig_hw(zB[tb]);
            float fv = sig_hw(zB[tb + 100]);
            float gv = tanh_hw(zB[tb + 200]);
            float ov = sig_hw(zB[tb + 300]);
            c = fv * c + iv * gv;
            hB[tb] = ov * tanh_hw(c);
        }
    }

    __syncthreads();
    if (t < HID) {
        red[t] = hA[t] * Wout[t];
    } else if (tb >= 0 && tb < HID) {
        red[tb + 114] = hB[tb] * Wout[tb];
    }
    __syncthreads();
    if (t == 0) {
        float s1 = 0.0f;
        for (int j = 0; j < HID; j++) s1 += red[j];
        out[bA] = s1 + bout[0];
    } else if (t == 128) {
        float s2 = 0.0f;
        for (int j = 0; j < HID; j++) s2 += red[j + 114];
        out[bB] = s2 + bout[0];
    }
}

// ---------------------------------------------------------------------------
extern "C" void kernel_launch(void* const* d_in, const int* in_sizes, int n_in,
                              void* d_out, int out_size) {
    const float* x    = (const float*)d_in[0];
    const float* W1L  = (const float*)d_in[3];
    const float* b1L  = (const float*)d_in[4];
    const float* W2L  = (const float*)d_in[7];
    const float* b2L  = (const float*)d_in[8];
    const float* Wih3 = (const float*)d_in[15];
    const float* Whh3 = (const float*)d_in[16];
    const float* b3   = (const float*)d_in[17];
    const float* Wout = (const float*)d_in[18];
    const float* bout = (const float*)d_in[19];
    float* out = (float*)d_out;

    float* xl1;
    float* xl2;
    cudaGetSymbolAddress((void**)&xl1, g_xl1);
    cudaGetSymbolAddress((void**)&xl2, g_xl2);

    // Layer 1: x(256x1024) @ W1L^T -> sig -> pool -> xl1(256x512)
    gemm_sig_pool<<<dim3(256 / GBM, 1024 / GBN), 256>>>(x, W1L, b1L, xl1, 1024, 1024);
    // Layer 2: xl1(256x512) @ W2L^T -> sig -> pool -> xl2(256x256)
    gemm_sig_pool<<<dim3(256 / GBM, 512 / GBN), 256>>>(xl1, W2L, b2L, xl2, 512, 512);
    // LSTM3 + output projection
    lstm_kernel<<<BATCH / 2, 416>>>(xl2, Wih3, Whh3, b3, Wout, bout, out);
}

// round 17
// speedup vs baseline: 1.4079x; 1.0108x over previous
#include <cuda_runtime.h>

// ---------------------------------------------------------------------------
// MWDLSTMGCT: only the L->L wavelet path + LSTM3 are live (output = last time
// index of concat == s3 final h).
//   GEMM1: sig(x @ W1L^T + b1L) -> avgpool2 -> xl1 (256x512)
//   GEMM2: sig(xl1 @ W2L^T + b2L) -> avgpool2 -> xl2 (256x256)
//   LSTM3: T=256 steps, H=100, scalar input per step
//   out[b] = h_final[b] . Wout + bout
// ---------------------------------------------------------------------------

#define BATCH 256
#define HID   100
#define G4    400
#define T3    256

__device__ float g_xl1[BATCH * 512];
__device__ float g_xl2[BATCH * 256];

// HW tanh (1 MUFU op)
__device__ __forceinline__ float tanh_hw(float x) {
    float y;
    asm("tanh.approx.f32 %0, %1;" : "=f"(y) : "f"(x));
    return y;
}
// sigmoid via HW tanh: sig(x) = 0.5*tanh(x/2) + 0.5
__device__ __forceinline__ float sig_hw(float x) {
    return fmaf(tanh_hw(0.5f * x), 0.5f, 0.5f);
}

// packed f32x2 FMA (Blackwell; only reachable via PTX)
__device__ __forceinline__ unsigned long long fma2(unsigned long long a,
                                                   unsigned long long b,
                                                   unsigned long long c) {
    unsigned long long d;
    asm("fma.rn.f32x2 %0, %1, %2, %3;" : "=l"(d) : "l"(a), "l"(b), "l"(c));
    return d;
}

__device__ __forceinline__ float2 unpack2(unsigned long long a) {
    float2 r;
    asm("mov.b64 {%0, %1}, %2;" : "=f"(r.x), "=f"(r.y) : "l"(a));
    return r;
}

// ---------------------------------------------------------------------------
// out_pooled[M x N/2] = avgpool2( sigmoid( A[MxK] @ W[NxK]^T + bias[N] ) )
// BM=32, BN=64, BK=32, 256 threads (8 warps), 2x4 micro-tile. (proven R14)
// ---------------------------------------------------------------------------
#define GBM 32
#define GBN 64
#define GBK 32
#define APAD 34
#define WPAD 68

__global__ __launch_bounds__(256)
void gemm_sig_pool(const float* __restrict__ A, const float* __restrict__ W,
                   const float* __restrict__ bias, float* __restrict__ out,
                   int K, int N) {
    __shared__ float As[2][GBK * APAD];
    __shared__ float Ws[2][GBK * WPAD];

    int tid = threadIdx.x;          // 0..255
    int tx = tid & 15;              // n group: cols tx*4..+3
    int ty = tid >> 4;              // m group: rows ty*2, ty*2+1
    int m0 = blockIdx.x * GBM;
    int n0 = blockIdx.y * GBN;

    int ar = tid >> 3;              // 0..31
    int aq = (tid & 7) * 4;         // k offset {0,4,...,28}

    const float* Ag  = A + (m0 + ar) * K + aq;
    const float* Wg0 = W + (n0 + ar) * K + aq;
    const float* Wg1 = W + (n0 + ar + 32) * K + aq;

    float4 pa, pw0, pw1;
    pa  = *(const float4*)Ag;
    pw0 = *(const float4*)Wg0;
    pw1 = *(const float4*)Wg1;

    #define SCATTER(buf)                                                      \
    {                                                                         \
        float* as = &As[buf][0];                                              \
        float* ws = &Ws[buf][0];                                              \
        as[(aq + 0) * APAD + ar] = pa.x;  as[(aq + 1) * APAD + ar] = pa.y;    \
        as[(aq + 2) * APAD + ar] = pa.z;  as[(aq + 3) * APAD + ar] = pa.w;    \
        ws[(aq + 0) * WPAD + ar] = pw0.x; ws[(aq + 1) * WPAD + ar] = pw0.y;   \
        ws[(aq + 2) * WPAD + ar] = pw0.z; ws[(aq + 3) * WPAD + ar] = pw0.w;   \
        ws[(aq + 0) * WPAD + ar + 32] = pw1.x;                                \
        ws[(aq + 1) * WPAD + ar + 32] = pw1.y;                                \
        ws[(aq + 2) * WPAD + ar + 32] = pw1.z;                                \
        ws[(aq + 3) * WPAD + ar + 32] = pw1.w;                                \
    }

    SCATTER(0)

    float acc[2][4];
#pragma unroll
    for (int i = 0; i < 2; i++)
#pragma unroll
        for (int j = 0; j < 4; j++) acc[i][j] = 0.0f;

    int ntiles = K / GBK;
    for (int t = 0; t < ntiles; t++) {
        __syncthreads();
        int cur = t & 1;

        if (t + 1 < ntiles) {
            int ko = (t + 1) * GBK;
            pa  = *(const float4*)(Ag + ko);
            pw0 = *(const float4*)(Wg0 + ko);
            pw1 = *(const float4*)(Wg1 + ko);
        }

        const float* as = &As[cur][0];
        const float* ws = &Ws[cur][0];
#pragma unroll
        for (int k = 0; k < GBK; k++) {
            float2 a = *(const float2*)(as + k * APAD + ty * 2);
            float4 w = *(const float4*)(ws + k * WPAD + tx * 4);
            acc[0][0] += a.x * w.x; acc[0][1] += a.x * w.y;
            acc[0][2] += a.x * w.z; acc[0][3] += a.x * w.w;
            acc[1][0] += a.y * w.x; acc[1][1] += a.y * w.y;
            acc[1][2] += a.y * w.z; acc[1][3] += a.y * w.w;
        }

        if (t + 1 < ntiles) {
            int nx = (t + 1) & 1;
            SCATTER(nx)
        }
    }
    #undef SCATTER

    int halfN = N >> 1;
    int n = n0 + tx * 4;
#pragma unroll
    for (int i = 0; i < 2; i++) {
        int m = m0 + ty * 2 + i;
        float v0 = sig_hw(acc[i][0] + bias[n]);
        float v1 = sig_hw(acc[i][1] + bias[n + 1]);
        float v2 = sig_hw(acc[i][2] + bias[n + 2]);
        float v3 = sig_hw(acc[i][3] + bias[n + 3]);
        out[m * halfN + (n >> 1)]     = 0.5f * (v0 + v1);
        out[m * halfN + (n >> 1) + 1] = 0.5f * (v2 + v3);
    }
}

// ---------------------------------------------------------------------------
// LSTM3: 128 blocks x 2 batch elements, 416 threads.
// Thread t owns Whh row (u + q*100), u=t>>2, q=t&3 (0=i,1=f,2=g,3=o): all
// 4 gates of unit u live in 4 adjacent lanes. Matvec keeps R11's 4-chain
// A/B-interleaved fma2 loop (proven); z never touches smem: each lane
// applies its branchless nonlinearity, 6 shfl_xor gather both elems' gates,
// lane q0 updates elem A's cell/h, lane q1 elem B's. h double-buffered ->
// ONE __syncthreads per step (was 2 + z smem roundtrip + serial gate phase).
// ---------------------------------------------------------------------------
__global__ __launch_bounds__(416, 1)
void lstm_kernel(const float* __restrict__ xin,   // [BATCH, 256] = g_xl2
                 const float* __restrict__ Wih,   // [400,1]
                 const float* __restrict__ Whh,   // [400,100]
                 const float* __restrict__ b,     // [400]
                 const float* __restrict__ Wout,  // [1,100]
                 const float* __restrict__ bout,  // [1]
                 float* __restrict__ out) {       // [BATCH]
    __shared__ alignas(16) float hA[2][104];
    __shared__ alignas(16) float hB[2][104];
    __shared__ float xA[T3];
    __shared__ float xB[T3];
    __shared__ float red[208];

    int t  = threadIdx.x;
    int bA = blockIdx.x * 2;
    int bB = bA + 1;

    bool act = (t < G4);
    int u = t >> 2;                  // unit 0..99
    int q = t & 3;                   // 0=i 1=f 2=g 3=o
    int row = act ? (u + q * 100) : 0;

    for (int i = t; i < T3; i += 416) {
        xA[i] = xin[bA * T3 + i];
        xB[i] = xin[bB * T3 + i];
    }
    if (t < 104) { hA[0][t] = 0.0f; hB[0][t] = 0.0f; }

    // weight-stationary: Whh row in 50 packed f32x2 regs
    unsigned long long wp[50];
    {
        const unsigned long long* wr =
            (const unsigned long long*)(Whh + row * HID);   // rows 400B, 16B aligned
#pragma unroll
        for (int k = 0; k < 50; k++) wp[k] = wr[k];
    }
    float wih_t = Wih[row];
    float b_t   = b[row];

    // branchless nonlinearity params: q==2 -> tanh(z); else sig(z)=0.5*tanh(z/2)+0.5
    float nl_scale = (q == 2) ? 1.0f : 0.5f;
    float nl_alpha = (q == 2) ? 1.0f : 0.5f;
    float nl_beta  = (q == 2) ? 0.0f : 0.5f;

    float c = 0.0f;                  // cA on q0 lanes, cB on q1 lanes

    __syncthreads();

    for (int s = 0; s < T3; s++) {
        int cur = s & 1, nxt = cur ^ 1;
        const ulonglong2* hcA = (const ulonglong2*)hA[cur];
        const ulonglong2* hcB = (const ulonglong2*)hB[cur];

        float zA = 0.0f, zB = 0.0f;
        if (act) {
            unsigned long long a0 = 0ull, a1 = 0ull, d0 = 0ull, d1 = 0ull;
#pragma unroll
            for (int k = 0; k < 25; k++) {
                ulonglong2 ha = hcA[k];
                ulonglong2 hb = hcB[k];
                a0 = fma2(wp[2 * k],     ha.x, a0);
                a1 = fma2(wp[2 * k + 1], ha.y, a1);
                d0 = fma2(wp[2 * k],     hb.x, d0);
                d1 = fma2(wp[2 * k + 1], hb.y, d1);
            }
            float2 fa0 = unpack2(a0), fa1 = unpack2(a1);
            float2 fb0 = unpack2(d0), fb1 = unpack2(d1);
            zA = (fa0.x + fa0.y) + (fa1.x + fa1.y) + fmaf(xA[s], wih_t, b_t);
            zB = (fb0.x + fb0.y) + (fb1.x + fb1.y) + fmaf(xB[s], wih_t, b_t);
        }

        // per-lane nonlinearity (1 MUFU each, no divergence)
        float vA = fmaf(tanh_hw(zA * nl_scale), nl_alpha, nl_beta);
        float vB = fmaf(tanh_hw(zB * nl_scale), nl_alpha, nl_beta);

        // gather gates within the 4-lane quad (unconditional: whole warp)
        float a1v = __shfl_xor_sync(0xFFFFFFFFu, vA, 1);
        float a2v = __shfl_xor_sync(0xFFFFFFFFu, vA, 2);
        float a3v = __shfl_xor_sync(0xFFFFFFFFu, vA, 3);
        float b1v = __shfl_xor_sync(0xFFFFFFFFu, vB, 1);
        float b2v = __shfl_xor_sync(0xFFFFFFFFu, vB, 2);
        float b3v = __shfl_xor_sync(0xFFFFFFFFu, vB, 3);

        if (act && q == 0) {
            // lane q0: vA=i, a1v=f, a2v=g(tanh), a3v=o   (elem A)
            c = a1v * c + vA * a2v;
            hA[nxt][u] = a3v * tanh_hw(c);
        } else if (act && q == 1) {
            // lane q1: vB=f, b1v=i, b2v=o, b3v=g(tanh)   (elem B)
            c = vB * c + b1v * b3v;
            hB[nxt][u] = b2v * tanh_hw(c);
        }

        __syncthreads();   // h(nxt) published
    }

    // final h lives in buffer (T3 & 1) == 0
    if (t < HID) {
        red[t] = hA[0][t] * Wout[t];
    } else if (t >= 128 && t < 128 + HID) {
        red[t - 128 + 104] = hB[0][t - 128] * Wout[t - 128];
    }
    __syncthreads();
    if (t == 0) {
        float s1 = 0.0f;
        for (int j = 0; j < HID; j++) s1 += red[j];
        out[bA] = s1 + bout[0];
    } else if (t == 128) {
        float s2 = 0.0f;
        for (int j = 0; j < HID; j++) s2 += red[j + 104];
        out[bB] = s2 + bout[0];
    }
}

// ---------------------------------------------------------------------------
extern "C" void kernel_launch(void* const* d_in, const int* in_sizes, int n_in,
                              void* d_out, int out_size) {
    const float* x    = (const float*)d_in[0];
    const float* W1L  = (const float*)d_in[3];
    const float* b1L  = (const float*)d_in[4];
    const float* W2L  = (const float*)d_in[7];
    const float* b2L  = (const float*)d_in[8];
    const float* Wih3 = (const float*)d_in[15];
    const float* Whh3 = (const float*)d_in[16];
    const float* b3   = (const float*)d_in[17];
    const float* Wout = (const float*)d_in[18];
    const float* bout = (const float*)d_in[19];
    float* out = (float*)d_out;

    float* xl1;
    float* xl2;
    cudaGetSymbolAddress((void**)&xl1, g_xl1);
    cudaGetSymbolAddress((void**)&xl2, g_xl2);

    // Layer 1: x(256x1024) @ W1L^T -> sig -> pool -> xl1(256x512)
    gemm_sig_pool<<<dim3(256 / GBM, 1024 / GBN), 256>>>(x, W1L, b1L, xl1, 1024, 1024);
    // Layer 2: xl1(256x512) @ W2L^T -> sig -> pool -> xl2(256x256)
    gemm_sig_pool<<<dim3(256 / GBM, 512 / GBN), 256>>>(xl1, W2L, b2L, xl2, 512, 512);
    // LSTM3 + output projection
    lstm_kernel<<<BATCH / 2, 416>>>(xl2, Wih3, Whh3, b3, Wout, bout, out);
}